// round 14
// baseline (speedup 1.0000x reference)
#include <cuda_runtime.h>

#define N_USERS 50000
#define N_ENT   150000
#define NN      200000
#define NE      2000000
#define NB      8192
#define TOT     176   // 64 + 64 + 32 + 16

// Scratch (allocation-free rule: __device__ globals; zero-initialized at load)
__device__ float g_ego [NN * 64];
__device__ float g_ego2[NN * 64];
__device__ float g_all [NN * TOT];
__device__ int   g_deg   [NN];
__device__ int   g_off   [NN];     // working copy of rowptr for placement
__device__ int   g_rowptr[NN];
__device__ int   g_total;
__device__ int2  g_edge  [NE];     // (col, bitcast(val)) grouped by row

// ---------------------------------------------------------------------------
// packed f32x2 helpers (FFMA2 only reachable via PTX)
__device__ __forceinline__ unsigned long long pk2(float a) {
    unsigned long long r;
    asm("mov.b64 %0, {%1, %1};" : "=l"(r) : "f"(a));
    return r;
}
__device__ __forceinline__ void ffma2(unsigned long long& d,
                                      unsigned long long a, unsigned long long b) {
    asm("fma.rn.f32x2 %0, %1, %2, %0;" : "+l"(d) : "l"(a), "l"(b));
}
__device__ __forceinline__ float2 upk2(unsigned long long v) {
    float x, y;
    asm("mov.b64 {%0, %1}, %2;" : "=f"(x), "=f"(y) : "l"(v));
    return make_float2(x, y);
}

// vector load/store helpers (V = floats per lane: 4 or 2)
template<int V> __device__ __forceinline__ void vload(float* d, const float* p);
template<> __device__ __forceinline__ void vload<4>(float* d, const float* p) {
    float4 t = *(const float4*)p; d[0] = t.x; d[1] = t.y; d[2] = t.z; d[3] = t.w;
}
template<> __device__ __forceinline__ void vload<2>(float* d, const float* p) {
    float2 t = *(const float2*)p; d[0] = t.x; d[1] = t.y;
}
template<int V> __device__ __forceinline__ void vstore(float* p, const float* s);
template<> __device__ __forceinline__ void vstore<4>(float* p, const float* s) {
    *(float4*)p = make_float4(s[0], s[1], s[2], s[3]);
}
template<> __device__ __forceinline__ void vstore<2>(float* p, const float* s) {
    *(float2*)p = make_float2(s[0], s[1]);
}

// ---------------------------------------------------------------------------
// Launch 0: ego/all init + degree histogram (g_deg zeroed by previous call's
// k_score; zero-initialized for the very first call).
__global__ void k_init_hist(const float* __restrict__ ue, const float* __restrict__ ee,
                            const int* __restrict__ rows) {
    int i = blockIdx.x * blockDim.x + threadIdx.x;   // over NN*16 = 3.2M
    if (i < NN * 16) {
        int n = i >> 4, c = i & 15;
        float4 v = (n < N_USERS)
            ? ((const float4*)ue)[(size_t)n * 16 + c]
            : ((const float4*)ee)[(size_t)(n - N_USERS) * 16 + c];
        ((float4*)g_ego)[i] = v;
        ((float4*)(g_all + (size_t)n * TOT))[c] = v;
    }
    if (i < NE) atomicAdd(&g_deg[rows[i]], 1);
}

// Launch 1: rowptr by atomic allocation (order-free; rows only need contiguity)
__global__ void k_alloc() {
    int n = blockIdx.x * blockDim.x + threadIdx.x;
    if (n >= NN) return;
    int d  = g_deg[n];
    int rp = atomicAdd(&g_total, d);
    g_rowptr[n] = rp;
    g_off[n]    = rp;
}

// Launch 2: scatter edges into CSR slots
__global__ void k_place(const int* __restrict__ rows, const int* __restrict__ cols,
                        const float* __restrict__ vals) {
    int e = blockIdx.x * blockDim.x + threadIdx.x;
    if (e >= NE) return;
    int r = rows[e];
    int p = atomicAdd(&g_off[r], 1);
    g_edge[p] = make_int2(cols[e], __float_as_int(vals[e]));
}

// ---------------------------------------------------------------------------
// Launches 3-5: fused side-gather + GC/BI transform + l2norm.
// Gather: HALF-WARP per node; each half loops to ITS OWN degree (no collective
// ops inside -> divergence is fine, no padding traffic); 2-way edge unroll.
// Matmul: node-tiled (NT=6) + packed FFMA2; lanes 0-15 GC, 16-31 BI.
template<int DIN, int DOUT, int OFF, int NT>
__global__ void __launch_bounds__(256, 4)
k_layer(const float* __restrict__ Wg, const float* __restrict__ bg,
        const float* __restrict__ Wb, const float* __restrict__ bb,
        const float* __restrict__ src, float* __restrict__ dst) {
    constexpr int V4  = DIN / 16;       // floats per lane in half-warp (4 or 2)
    constexpr int LPM = DOUT / 4;       // active lanes per matrix
    constexpr int WPB = 8;
    extern __shared__ __align__(16) float sdyn[];
    float* sW = sdyn;                                   // 2*DIN*DOUT
    typedef float SxTile[NT][2][DIN];
    SxTile* sx = reinterpret_cast<SxTile*>(sdyn + 2 * DIN * DOUT);  // [WPB]
    __shared__ __align__(16) float sB[2 * DOUT];

    int tid = threadIdx.x;
    for (int i = tid; i < DIN * DOUT; i += blockDim.x) { sW[i] = Wg[i]; sW[DIN * DOUT + i] = Wb[i]; }
    for (int i = tid; i < DOUT; i += blockDim.x)       { sB[i] = bg[i]; sB[DOUT + i] = bb[i]; }
    __syncthreads();

    int w = tid >> 5, lane = tid & 31;
    int h  = lane >> 4;                 // half id: gather node select / matmul GC-BI
    int jl = lane & 15;
    int jc = (jl < LPM) ? jl : 0;
    const float* wbase = sW + h * DIN * DOUT;

    for (int nb = (blockIdx.x * WPB + w) * NT; nb < NN; nb += gridDim.x * WPB * NT) {
        // ---- gather NT nodes, two at a time (one per half-warp) ----
        #pragma unroll 1
        for (int tp = 0; tp < NT; tp += 2) {
            int n = nb + tp + h;
            bool act = n < NN;
            float er[V4], a0[V4], a1[V4];
            #pragma unroll
            for (int c = 0; c < V4; c++) { er[c] = 0.f; a0[c] = 0.f; a1[c] = 0.f; }
            int s0 = 0, cnt = 0;
            if (act) {
                s0  = g_rowptr[n];
                cnt = g_deg[n];
                vload<V4>(er, src + (size_t)n * DIN + V4 * jl);
            }
            // per-half loop bound: no collective ops inside, divergence is fine
            for (int m = 0; m < cnt; m += 2) {
                int2 e0 = __ldg(&g_edge[s0 + m]);
                int2 e1 = (m + 1 < cnt) ? __ldg(&g_edge[s0 + m + 1]) : make_int2(0, 0);
                float x0[V4], x1[V4];
                vload<V4>(x0, src + (size_t)e0.x * DIN + V4 * jl);
                vload<V4>(x1, src + (size_t)e1.x * DIN + V4 * jl);
                float v0 = __int_as_float(e0.y);
                float v1 = __int_as_float(e1.y);
                #pragma unroll
                for (int c = 0; c < V4; c++) {
                    a0[c] = fmaf(v0, x0[c], a0[c]);
                    a1[c] = fmaf(v1, x1[c], a1[c]);
                }
            }
            float s1v[V4], s2v[V4];
            #pragma unroll
            for (int c = 0; c < V4; c++) {
                float acc = a0[c] + a1[c];
                s1v[c] = er[c] + acc;
                s2v[c] = er[c] * acc;
            }
            if (tp + h < NT) {
                vstore<V4>(&sx[w][tp + h][0][V4 * jl], s1v);
                vstore<V4>(&sx[w][tp + h][1][V4 * jl], s2v);
            }
        }
        __syncwarp();

        // ---- node-tiled matmul with packed FFMA2 ----
        unsigned long long p01[NT], p23[NT];
        #pragma unroll
        for (int t = 0; t < NT; t++) { p01[t] = 0ull; p23[t] = 0ull; }

        #pragma unroll 2
        for (int k4 = 0; k4 < DIN; k4 += 4) {
            ulonglong2 wv0 = ((const ulonglong2*)(wbase + (k4 + 0) * DOUT))[jc];
            ulonglong2 wv1 = ((const ulonglong2*)(wbase + (k4 + 1) * DOUT))[jc];
            ulonglong2 wv2 = ((const ulonglong2*)(wbase + (k4 + 2) * DOUT))[jc];
            ulonglong2 wv3 = ((const ulonglong2*)(wbase + (k4 + 3) * DOUT))[jc];
            #pragma unroll
            for (int t = 0; t < NT; t++) {
                float4 xv = *(const float4*)(&sx[w][t][h][k4]);
                unsigned long long x0 = pk2(xv.x), x1 = pk2(xv.y);
                unsigned long long x2 = pk2(xv.z), x3 = pk2(xv.w);
                ffma2(p01[t], x0, wv0.x); ffma2(p23[t], x0, wv0.y);
                ffma2(p01[t], x1, wv1.x); ffma2(p23[t], x1, wv1.y);
                ffma2(p01[t], x2, wv2.x); ffma2(p23[t], x2, wv2.y);
                ffma2(p01[t], x3, wv3.x); ffma2(p23[t], x3, wv3.y);
            }
        }

        float4 bv = ((const float4*)(sB + h * DOUT))[jc];
        #pragma unroll
        for (int t = 0; t < NT; t++) {
            int n = nb + t;
            float2 a01 = upk2(p01[t]), a23 = upk2(p23[t]);
            float4 v;
            v.x = a01.x + bv.x; v.x = v.x > 0.f ? v.x : 0.01f * v.x;
            v.y = a01.y + bv.y; v.y = v.y > 0.f ? v.y : 0.01f * v.y;
            v.z = a23.x + bv.z; v.z = v.z > 0.f ? v.z : 0.01f * v.z;
            v.w = a23.y + bv.w; v.w = v.w > 0.f ? v.w : 0.01f * v.w;
            float4 o;
            o.x = v.x + __shfl_xor_sync(0xffffffffu, v.x, 16);
            o.y = v.y + __shfl_xor_sync(0xffffffffu, v.y, 16);
            o.z = v.z + __shfl_xor_sync(0xffffffffu, v.z, 16);
            o.w = v.w + __shfl_xor_sync(0xffffffffu, v.w, 16);
            float ss = o.x * o.x + o.y * o.y + o.z * o.z + o.w * o.w;
            #pragma unroll
            for (int off = LPM / 2; off > 0; off >>= 1)
                ss += __shfl_xor_sync(0xffffffffu, ss, off);
            float inv = 1.0f / fmaxf(sqrtf(ss), 1e-12f);
            if (n < NN && h == 0 && jl < LPM) {
                ((float4*)(dst + (size_t)n * DOUT))[jl] = o;
                float4 on = make_float4(o.x * inv, o.y * inv, o.z * inv, o.w * inv);
                ((float4*)(g_all + (size_t)n * TOT + OFF))[jl] = on;
            }
        }
        __syncwarp();
    }
}

// ---------------------------------------------------------------------------
// Launch 6: scoring + reset g_deg/g_total for the next call (grid covers NN).
__global__ void k_score(const int* __restrict__ users, const int* __restrict__ pos,
                        const int* __restrict__ neg, float* __restrict__ out) {
    int gi = blockIdx.x * blockDim.x + threadIdx.x;
    if (gi < NN) g_deg[gi] = 0;
    if (gi == 0) g_total = 0;

    int wid  = gi >> 5;
    int lane = threadIdx.x & 31;
    if (wid >= NB) return;
    const float* u = g_all + (size_t)users[wid] * TOT;
    const float* p = g_all + (size_t)(N_USERS + pos[wid]) * TOT;
    const float* q = g_all + (size_t)(N_USERS + neg[wid]) * TOT;
    float sp = 0.f, sn = 0.f;
    #pragma unroll
    for (int k = lane; k < TOT; k += 32) {
        float uv = u[k];
        sp += uv * p[k];
        sn += uv * q[k];
    }
    #pragma unroll
    for (int o = 16; o > 0; o >>= 1) {
        sp += __shfl_xor_sync(0xffffffffu, sp, o);
        sn += __shfl_xor_sync(0xffffffffu, sn, o);
    }
    if (lane == 0) { out[2 * wid] = sp; out[2 * wid + 1] = sn; }
}

// ---------------------------------------------------------------------------
extern "C" void kernel_launch(void* const* d_in, const int* in_sizes, int n_in,
                              void* d_out, int out_size) {
    const int*   users = (const int*)  d_in[0];
    const int*   pos   = (const int*)  d_in[1];
    const int*   neg   = (const int*)  d_in[2];
    const int*   rows  = (const int*)  d_in[3];
    const int*   cols  = (const int*)  d_in[4];
    const float* vals  = (const float*)d_in[5];
    const float* ue    = (const float*)d_in[6];
    const float* ee    = (const float*)d_in[7];
    const float* W[3][4];
    for (int l = 0; l < 3; l++)
        for (int j = 0; j < 4; j++)
            W[l][j] = (const float*)d_in[8 + 4 * l + j];

    float *p_ego, *p_ego2;
    cudaGetSymbolAddress((void**)&p_ego,  g_ego);
    cudaGetSymbolAddress((void**)&p_ego2, g_ego2);

    const int TB  = 256;
    const int TBL = 256;   // 8 warps per block for k_layer
    const int GL  = 592;   // 4 blocks/SM * 148 SMs

    // dynamic smem: weights (2*DIN*DOUT) + node tiles (WPB*NT*2*DIN), floats
    const int SM0 = (2 * 64 * 64 + 8 * 6 * 2 * 64) * 4;   // 57344 -> 4 blocks/SM (224KB)
    const int SM1 = (2 * 64 * 32 + 8 * 6 * 2 * 64) * 4;   // 40960
    const int SM2 = (2 * 32 * 16 + 8 * 6 * 2 * 32) * 4;   // 16384
    cudaFuncSetAttribute(k_layer<64, 64,  64, 6>, cudaFuncAttributeMaxDynamicSharedMemorySize, SM0);
    cudaFuncSetAttribute(k_layer<64, 32, 128, 6>, cudaFuncAttributeMaxDynamicSharedMemorySize, SM1);
    cudaFuncSetAttribute(k_layer<32, 16, 160, 6>, cudaFuncAttributeMaxDynamicSharedMemorySize, SM2);

    // 0: init + histogram
    k_init_hist<<<(NN * 16 + TB - 1) / TB, TB>>>(ue, ee, rows);
    // 1: rowptr by atomic allocation
    k_alloc<<<(NN + TB - 1) / TB, TB>>>();
    // 2: CSR placement
    k_place<<<(NE + TB - 1) / TB, TB>>>(rows, cols, vals);

    // 3-5: fused layers  (launch index 3 = ncu capture slot)
    k_layer<64, 64,  64, 6><<<GL, TBL, SM0>>>(W[0][0], W[0][1], W[0][2], W[0][3], p_ego,  p_ego2);
    k_layer<64, 32, 128, 6><<<GL, TBL, SM1>>>(W[1][0], W[1][1], W[1][2], W[1][3], p_ego2, p_ego);
    k_layer<32, 16, 160, 6><<<GL, TBL, SM2>>>(W[2][0], W[2][1], W[2][2], W[2][3], p_ego,  p_ego2);

    // 6: score + scratch reset
    k_score<<<(NB * 32 + TB - 1) / TB, TB>>>(users, pos, neg, (float*)d_out);
}

// round 15
// speedup vs baseline: 1.1400x; 1.1400x over previous
#include <cuda_runtime.h>

#define N_USERS 50000
#define N_ENT   150000
#define NN      200000
#define NE      2000000
#define NB      8192
#define TOT     176   // 64 + 64 + 32 + 16

// Scratch (allocation-free rule: __device__ globals; zero-initialized at load)
__device__ float g_ego [NN * 64];
__device__ float g_ego2[NN * 64];
__device__ float g_all [NN * TOT];
__device__ int   g_deg   [NN];
__device__ int   g_off   [NN];     // working copy of rowptr for placement
__device__ int   g_rowptr[NN];
__device__ int   g_total;
__device__ int2  g_edge  [NE];     // (col, bitcast(val)) grouped by row

// ---------------------------------------------------------------------------
// packed f32x2 helpers (FFMA2 only reachable via PTX)
__device__ __forceinline__ unsigned long long pk2(float a) {
    unsigned long long r;
    asm("mov.b64 %0, {%1, %1};" : "=l"(r) : "f"(a));
    return r;
}
__device__ __forceinline__ void ffma2(unsigned long long& d,
                                      unsigned long long a, unsigned long long b) {
    asm("fma.rn.f32x2 %0, %1, %2, %0;" : "+l"(d) : "l"(a), "l"(b));
}
__device__ __forceinline__ float2 upk2(unsigned long long v) {
    float x, y;
    asm("mov.b64 {%0, %1}, %2;" : "=f"(x), "=f"(y) : "l"(v));
    return make_float2(x, y);
}

// vector load/store helpers (V = floats per lane: 4 or 2)
template<int V> __device__ __forceinline__ void vload(float* d, const float* p);
template<> __device__ __forceinline__ void vload<4>(float* d, const float* p) {
    float4 t = *(const float4*)p; d[0] = t.x; d[1] = t.y; d[2] = t.z; d[3] = t.w;
}
template<> __device__ __forceinline__ void vload<2>(float* d, const float* p) {
    float2 t = *(const float2*)p; d[0] = t.x; d[1] = t.y;
}
template<int V> __device__ __forceinline__ void vstore(float* p, const float* s);
template<> __device__ __forceinline__ void vstore<4>(float* p, const float* s) {
    *(float4*)p = make_float4(s[0], s[1], s[2], s[3]);
}
template<> __device__ __forceinline__ void vstore<2>(float* p, const float* s) {
    *(float2*)p = make_float2(s[0], s[1]);
}

// ---------------------------------------------------------------------------
// Launch 0: ego/all init + degree histogram (g_deg zeroed by previous call's
// k_score; zero-initialized for the very first call).
__global__ void k_init_hist(const float* __restrict__ ue, const float* __restrict__ ee,
                            const int* __restrict__ rows) {
    int i = blockIdx.x * blockDim.x + threadIdx.x;   // over NN*16 = 3.2M
    if (i < NN * 16) {
        int n = i >> 4, c = i & 15;
        float4 v = (n < N_USERS)
            ? ((const float4*)ue)[(size_t)n * 16 + c]
            : ((const float4*)ee)[(size_t)(n - N_USERS) * 16 + c];
        ((float4*)g_ego)[i] = v;
        ((float4*)(g_all + (size_t)n * TOT))[c] = v;
    }
    if (i < NE) atomicAdd(&g_deg[rows[i]], 1);
}

// Launch 1: rowptr by atomic allocation (order-free; rows only need contiguity)
__global__ void k_alloc() {
    int n = blockIdx.x * blockDim.x + threadIdx.x;
    if (n >= NN) return;
    int d  = g_deg[n];
    int rp = atomicAdd(&g_total, d);
    g_rowptr[n] = rp;
    g_off[n]    = rp;
}

// Launch 2: scatter edges into CSR slots
__global__ void k_place(const int* __restrict__ rows, const int* __restrict__ cols,
                        const float* __restrict__ vals) {
    int e = blockIdx.x * blockDim.x + threadIdx.x;
    if (e >= NE) return;
    int r = rows[e];
    int p = atomicAdd(&g_off[r], 1);
    g_edge[p] = make_int2(cols[e], __float_as_int(vals[e]));
}

// ---------------------------------------------------------------------------
// Launches 3-5: fused side-gather + GC/BI transform + l2norm.
// Gather: HALF-WARP per node (lanes 0-15 node A, 16-31 node B); each half
// loops to ITS OWN degree (no collective ops inside -> divergence legal);
// 2-way edge unroll -> 4 independent LDG chains per warp.
// Matmul: node-tiled (NT=4) + packed FFMA2; lanes 0-15 GC, 16-31 BI.
template<int DIN, int DOUT, int OFF>
__global__ void __launch_bounds__(256, 4)
k_layer(const float* __restrict__ Wg, const float* __restrict__ bg,
        const float* __restrict__ Wb, const float* __restrict__ bb,
        const float* __restrict__ src, float* __restrict__ dst) {
    constexpr int V4  = DIN / 16;       // floats per lane in half-warp (4 or 2)
    constexpr int LPM = DOUT / 4;       // active lanes per matrix
    constexpr int NT  = 4;              // nodes per warp per matmul pass
    constexpr int WPB = 8;
    extern __shared__ __align__(16) float sdyn[];
    float* sW = sdyn;                                   // 2*DIN*DOUT
    typedef float SxTile[NT][2][DIN];
    SxTile* sx = reinterpret_cast<SxTile*>(sdyn + 2 * DIN * DOUT);  // [WPB]
    __shared__ __align__(16) float sB[2 * DOUT];

    int tid = threadIdx.x;
    for (int i = tid; i < DIN * DOUT; i += blockDim.x) { sW[i] = Wg[i]; sW[DIN * DOUT + i] = Wb[i]; }
    for (int i = tid; i < DOUT; i += blockDim.x)       { sB[i] = bg[i]; sB[DOUT + i] = bb[i]; }
    __syncthreads();

    int w = tid >> 5, lane = tid & 31;
    int h  = lane >> 4;                 // half id: gather node select / matmul GC-BI
    int jl = lane & 15;
    int jc = (jl < LPM) ? jl : 0;
    const float* wbase = sW + h * DIN * DOUT;

    for (int nb = (blockIdx.x * WPB + w) * NT; nb < NN; nb += gridDim.x * WPB * NT) {
        // ---- gather NT nodes, two at a time (one per half-warp) ----
        #pragma unroll 1
        for (int tp = 0; tp < NT; tp += 2) {
            int n = nb + tp + h;
            bool act = n < NN;
            float er[V4], a0[V4], a1[V4];
            #pragma unroll
            for (int c = 0; c < V4; c++) { er[c] = 0.f; a0[c] = 0.f; a1[c] = 0.f; }
            int s0 = 0, cnt = 0;
            if (act) {
                s0  = g_rowptr[n];
                cnt = g_deg[n];
                vload<V4>(er, src + (size_t)n * DIN + V4 * jl);
            }
            // per-half loop bound: no collective ops inside, divergence is legal
            for (int m = 0; m < cnt; m += 2) {
                int2 e0 = __ldg(&g_edge[s0 + m]);
                int2 e1 = (m + 1 < cnt) ? __ldg(&g_edge[s0 + m + 1]) : make_int2(0, 0);
                float x0[V4], x1[V4];
                vload<V4>(x0, src + (size_t)e0.x * DIN + V4 * jl);
                vload<V4>(x1, src + (size_t)e1.x * DIN + V4 * jl);
                float v0 = __int_as_float(e0.y);
                float v1 = __int_as_float(e1.y);
                #pragma unroll
                for (int c = 0; c < V4; c++) {
                    a0[c] = fmaf(v0, x0[c], a0[c]);
                    a1[c] = fmaf(v1, x1[c], a1[c]);
                }
            }
            float s1v[V4], s2v[V4];
            #pragma unroll
            for (int c = 0; c < V4; c++) {
                float acc = a0[c] + a1[c];
                s1v[c] = er[c] + acc;
                s2v[c] = er[c] * acc;
            }
            vstore<V4>(&sx[w][tp + h][0][V4 * jl], s1v);
            vstore<V4>(&sx[w][tp + h][1][V4 * jl], s2v);
        }
        __syncwarp();

        // ---- node-tiled matmul with packed FFMA2 ----
        unsigned long long p01[NT], p23[NT];
        #pragma unroll
        for (int t = 0; t < NT; t++) { p01[t] = 0ull; p23[t] = 0ull; }

        #pragma unroll
        for (int k4 = 0; k4 < DIN; k4 += 4) {
            float4 xv[NT];
            #pragma unroll
            for (int t = 0; t < NT; t++)
                xv[t] = *(const float4*)(&sx[w][t][h][k4]);
            #pragma unroll
            for (int i = 0; i < 4; i++) {
                ulonglong2 wv = ((const ulonglong2*)(wbase + (k4 + i) * DOUT))[jc];
                #pragma unroll
                for (int t = 0; t < NT; t++) {
                    unsigned long long xx = pk2((&xv[t].x)[i]);
                    ffma2(p01[t], xx, wv.x);
                    ffma2(p23[t], xx, wv.y);
                }
            }
        }

        float4 bv = ((const float4*)(sB + h * DOUT))[jc];
        #pragma unroll
        for (int t = 0; t < NT; t++) {
            int n = nb + t;
            float2 a01 = upk2(p01[t]), a23 = upk2(p23[t]);
            float4 v;
            v.x = a01.x + bv.x; v.x = v.x > 0.f ? v.x : 0.01f * v.x;
            v.y = a01.y + bv.y; v.y = v.y > 0.f ? v.y : 0.01f * v.y;
            v.z = a23.x + bv.z; v.z = v.z > 0.f ? v.z : 0.01f * v.z;
            v.w = a23.y + bv.w; v.w = v.w > 0.f ? v.w : 0.01f * v.w;
            float4 o;
            o.x = v.x + __shfl_xor_sync(0xffffffffu, v.x, 16);
            o.y = v.y + __shfl_xor_sync(0xffffffffu, v.y, 16);
            o.z = v.z + __shfl_xor_sync(0xffffffffu, v.z, 16);
            o.w = v.w + __shfl_xor_sync(0xffffffffu, v.w, 16);
            float ss = o.x * o.x + o.y * o.y + o.z * o.z + o.w * o.w;
            #pragma unroll
            for (int off = LPM / 2; off > 0; off >>= 1)
                ss += __shfl_xor_sync(0xffffffffu, ss, off);
            float inv = 1.0f / fmaxf(sqrtf(ss), 1e-12f);
            if (n < NN && h == 0 && jl < LPM) {
                ((float4*)(dst + (size_t)n * DOUT))[jl] = o;
                float4 on = make_float4(o.x * inv, o.y * inv, o.z * inv, o.w * inv);
                ((float4*)(g_all + (size_t)n * TOT + OFF))[jl] = on;
            }
        }
        __syncwarp();
    }
}

// ---------------------------------------------------------------------------
// Launch 6: scoring + reset g_deg/g_total for the next call (grid covers NN).
__global__ void k_score(const int* __restrict__ users, const int* __restrict__ pos,
                        const int* __restrict__ neg, float* __restrict__ out) {
    int gi = blockIdx.x * blockDim.x + threadIdx.x;
    if (gi < NN) g_deg[gi] = 0;
    if (gi == 0) g_total = 0;

    int wid  = gi >> 5;
    int lane = threadIdx.x & 31;
    if (wid >= NB) return;
    const float* u = g_all + (size_t)users[wid] * TOT;
    const float* p = g_all + (size_t)(N_USERS + pos[wid]) * TOT;
    const float* q = g_all + (size_t)(N_USERS + neg[wid]) * TOT;
    float sp = 0.f, sn = 0.f;
    #pragma unroll
    for (int k = lane; k < TOT; k += 32) {
        float uv = u[k];
        sp += uv * p[k];
        sn += uv * q[k];
    }
    #pragma unroll
    for (int o = 16; o > 0; o >>= 1) {
        sp += __shfl_xor_sync(0xffffffffu, sp, o);
        sn += __shfl_xor_sync(0xffffffffu, sn, o);
    }
    if (lane == 0) { out[2 * wid] = sp; out[2 * wid + 1] = sn; }
}

// ---------------------------------------------------------------------------
extern "C" void kernel_launch(void* const* d_in, const int* in_sizes, int n_in,
                              void* d_out, int out_size) {
    const int*   users = (const int*)  d_in[0];
    const int*   pos   = (const int*)  d_in[1];
    const int*   neg   = (const int*)  d_in[2];
    const int*   rows  = (const int*)  d_in[3];
    const int*   cols  = (const int*)  d_in[4];
    const float* vals  = (const float*)d_in[5];
    const float* ue    = (const float*)d_in[6];
    const float* ee    = (const float*)d_in[7];
    const float* W[3][4];
    for (int l = 0; l < 3; l++)
        for (int j = 0; j < 4; j++)
            W[l][j] = (const float*)d_in[8 + 4 * l + j];

    float *p_ego, *p_ego2;
    cudaGetSymbolAddress((void**)&p_ego,  g_ego);
    cudaGetSymbolAddress((void**)&p_ego2, g_ego2);

    const int TB  = 256;
    const int TBL = 256;   // 8 warps per block for k_layer
    const int GL  = 592;   // 4 blocks/SM * 148 SMs

    // dynamic smem: weights (2*DIN*DOUT) + node tiles (WPB*NT*2*DIN), floats
    // NT=4 keeps layer-0 at 49152B -> 4 blocks/SM (incl. ~1KB/block reserve)
    const int SM0 = (2 * 64 * 64 + 8 * 4 * 2 * 64) * 4;   // 49152
    const int SM1 = (2 * 64 * 32 + 8 * 4 * 2 * 64) * 4;   // 32768
    const int SM2 = (2 * 32 * 16 + 8 * 4 * 2 * 32) * 4;   // 12288
    cudaFuncSetAttribute(k_layer<64, 64,  64>, cudaFuncAttributeMaxDynamicSharedMemorySize, SM0);
    cudaFuncSetAttribute(k_layer<64, 32, 128>, cudaFuncAttributeMaxDynamicSharedMemorySize, SM1);
    cudaFuncSetAttribute(k_layer<32, 16, 160>, cudaFuncAttributeMaxDynamicSharedMemorySize, SM2);

    // 0: init + histogram
    k_init_hist<<<(NN * 16 + TB - 1) / TB, TB>>>(ue, ee, rows);
    // 1: rowptr by atomic allocation
    k_alloc<<<(NN + TB - 1) / TB, TB>>>();
    // 2: CSR placement
    k_place<<<(NE + TB - 1) / TB, TB>>>(rows, cols, vals);

    // 3-5: fused layers  (launch index 3 = ncu capture slot)
    k_layer<64, 64,  64><<<GL, TBL, SM0>>>(W[0][0], W[0][1], W[0][2], W[0][3], p_ego,  p_ego2);
    k_layer<64, 32, 128><<<GL, TBL, SM1>>>(W[1][0], W[1][1], W[1][2], W[1][3], p_ego2, p_ego);
    k_layer<32, 16, 160><<<GL, TBL, SM2>>>(W[2][0], W[2][1], W[2][2], W[2][3], p_ego,  p_ego2);

    // 6: score + scratch reset
    k_score<<<(NB * 32 + TB - 1) / TB, TB>>>(users, pos, neg, (float*)d_out);
}

// round 16
// speedup vs baseline: 1.6316x; 1.4313x over previous
#include <cuda_runtime.h>

#define N_USERS 50000
#define N_ENT   150000
#define NN      200000
#define NE      2000000
#define NB      8192
#define TOT     176   // 64 + 64 + 32 + 16

// Scratch (allocation-free rule: __device__ globals; zero-initialized at load)
__device__ float g_ego [NN * 64];
__device__ float g_ego2[NN * 64];
__device__ float g_all [NN * TOT];
__device__ int   g_deg   [NN];
__device__ int   g_off   [NN];     // working copy of rowptr for placement
__device__ int   g_rowptr[NN];
__device__ int   g_total;
__device__ int2  g_edge  [NE];     // (col, bitcast(val)) grouped by row

// ---------------------------------------------------------------------------
// packed f32x2 helpers (FFMA2 only reachable via PTX)
__device__ __forceinline__ unsigned long long pk2(float a) {
    unsigned long long r;
    asm("mov.b64 %0, {%1, %1};" : "=l"(r) : "f"(a));
    return r;
}
__device__ __forceinline__ void ffma2(unsigned long long& d,
                                      unsigned long long a, unsigned long long b) {
    asm("fma.rn.f32x2 %0, %1, %2, %0;" : "+l"(d) : "l"(a), "l"(b));
}
__device__ __forceinline__ float2 upk2(unsigned long long v) {
    float x, y;
    asm("mov.b64 {%0, %1}, %2;" : "=f"(x), "=f"(y) : "l"(v));
    return make_float2(x, y);
}

// vector load/store helpers (V = floats per lane: 4 or 2)
template<int V> __device__ __forceinline__ void vload(float* d, const float* p);
template<> __device__ __forceinline__ void vload<4>(float* d, const float* p) {
    float4 t = *(const float4*)p; d[0] = t.x; d[1] = t.y; d[2] = t.z; d[3] = t.w;
}
template<> __device__ __forceinline__ void vload<2>(float* d, const float* p) {
    float2 t = *(const float2*)p; d[0] = t.x; d[1] = t.y;
}
template<int V> __device__ __forceinline__ void vstore(float* p, const float* s);
template<> __device__ __forceinline__ void vstore<4>(float* p, const float* s) {
    *(float4*)p = make_float4(s[0], s[1], s[2], s[3]);
}
template<> __device__ __forceinline__ void vstore<2>(float* p, const float* s) {
    *(float2*)p = make_float2(s[0], s[1]);
}

// ---------------------------------------------------------------------------
// Launch 0: ego/all init + degree histogram (g_deg zeroed by previous call's
// k_score; zero-initialized for the very first call).
__global__ void k_init_hist(const float* __restrict__ ue, const float* __restrict__ ee,
                            const int* __restrict__ rows) {
    int i = blockIdx.x * blockDim.x + threadIdx.x;   // over NN*16 = 3.2M
    if (i < NN * 16) {
        int n = i >> 4, c = i & 15;
        float4 v = (n < N_USERS)
            ? ((const float4*)ue)[(size_t)n * 16 + c]
            : ((const float4*)ee)[(size_t)(n - N_USERS) * 16 + c];
        ((float4*)g_ego)[i] = v;
        ((float4*)(g_all + (size_t)n * TOT))[c] = v;
    }
    if (i < NE) atomicAdd(&g_deg[rows[i]], 1);
}

// Launch 1: rowptr by atomic allocation (order-free; rows only need contiguity)
__global__ void k_alloc() {
    int n = blockIdx.x * blockDim.x + threadIdx.x;
    if (n >= NN) return;
    int d  = g_deg[n];
    int rp = atomicAdd(&g_total, d);
    g_rowptr[n] = rp;
    g_off[n]    = rp;
}

// Launch 2: scatter edges into CSR slots
__global__ void k_place(const int* __restrict__ rows, const int* __restrict__ cols,
                        const float* __restrict__ vals) {
    int e = blockIdx.x * blockDim.x + threadIdx.x;
    if (e >= NE) return;
    int r = rows[e];
    int p = atomicAdd(&g_off[r], 1);
    g_edge[p] = make_int2(cols[e], __float_as_int(vals[e]));
}

// ---------------------------------------------------------------------------
// Launches 3-5: fused side-gather + GC/BI transform + l2norm.
// Gather (round-13 proven): HALF-WARP per node, LOCKSTEP to warp-max degree
// with (0,0)-padded edges (one warp-wide LDG serves both halves); 2-way unroll.
// Matmul: node-tiled (per-layer NT) + packed FFMA2; lanes 0-15 GC, 16-31 BI.
template<int DIN, int DOUT, int OFF, int NT>
__global__ void __launch_bounds__(256, 4)
k_layer(const float* __restrict__ Wg, const float* __restrict__ bg,
        const float* __restrict__ Wb, const float* __restrict__ bb,
        const float* __restrict__ src, float* __restrict__ dst) {
    constexpr int V4  = DIN / 16;       // floats per lane in half-warp (4 or 2)
    constexpr int LPM = DOUT / 4;       // active lanes per matrix
    constexpr int WPB = 8;
    extern __shared__ __align__(16) float sdyn[];
    float* sW = sdyn;                                   // 2*DIN*DOUT
    typedef float SxTile[NT][2][DIN];
    SxTile* sx = reinterpret_cast<SxTile*>(sdyn + 2 * DIN * DOUT);  // [WPB]
    __shared__ __align__(16) float sB[2 * DOUT];

    int tid = threadIdx.x;
    for (int i = tid; i < DIN * DOUT; i += blockDim.x) { sW[i] = Wg[i]; sW[DIN * DOUT + i] = Wb[i]; }
    for (int i = tid; i < DOUT; i += blockDim.x)       { sB[i] = bg[i]; sB[DOUT + i] = bb[i]; }
    __syncthreads();

    int w = tid >> 5, lane = tid & 31;
    int h  = lane >> 4;                 // half id: gather node select / matmul GC-BI
    int jl = lane & 15;
    int jc = (jl < LPM) ? jl : 0;
    const float* wbase = sW + h * DIN * DOUT;

    for (int nb = (blockIdx.x * WPB + w) * NT; nb < NN; nb += gridDim.x * WPB * NT) {
        // ---- gather NT nodes, two at a time (one per half-warp), lockstep ----
        #pragma unroll 1
        for (int tp = 0; tp < NT; tp += 2) {
            int n = nb + tp + h;
            bool act = n < NN;
            float er[V4], a0[V4], a1[V4];
            #pragma unroll
            for (int c = 0; c < V4; c++) { er[c] = 0.f; a0[c] = 0.f; a1[c] = 0.f; }
            int s0 = 0, cnt = 0;
            if (act) {
                s0  = g_rowptr[n];
                cnt = g_deg[n];
                vload<V4>(er, src + (size_t)n * DIN + V4 * jl);
            }
            int cmax = cnt;
            #pragma unroll
            for (int o = 16; o > 0; o >>= 1)
                cmax = max(cmax, __shfl_xor_sync(0xffffffffu, cmax, o));
            for (int m = 0; m < cmax; m += 2) {
                int2 e0 = (m     < cnt) ? __ldg(&g_edge[s0 + m])     : make_int2(0, 0);
                int2 e1 = (m + 1 < cnt) ? __ldg(&g_edge[s0 + m + 1]) : make_int2(0, 0);
                float x0[V4], x1[V4];
                vload<V4>(x0, src + (size_t)e0.x * DIN + V4 * jl);
                vload<V4>(x1, src + (size_t)e1.x * DIN + V4 * jl);
                float v0 = __int_as_float(e0.y);
                float v1 = __int_as_float(e1.y);
                #pragma unroll
                for (int c = 0; c < V4; c++) {
                    a0[c] = fmaf(v0, x0[c], a0[c]);
                    a1[c] = fmaf(v1, x1[c], a1[c]);
                }
            }
            float s1v[V4], s2v[V4];
            #pragma unroll
            for (int c = 0; c < V4; c++) {
                float acc = a0[c] + a1[c];
                s1v[c] = er[c] + acc;
                s2v[c] = er[c] * acc;
            }
            vstore<V4>(&sx[w][tp + h][0][V4 * jl], s1v);
            vstore<V4>(&sx[w][tp + h][1][V4 * jl], s2v);
        }
        __syncwarp();

        // ---- node-tiled matmul with packed FFMA2 (wv-preload form) ----
        unsigned long long p01[NT], p23[NT];
        #pragma unroll
        for (int t = 0; t < NT; t++) { p01[t] = 0ull; p23[t] = 0ull; }

        #pragma unroll 2
        for (int k4 = 0; k4 < DIN; k4 += 4) {
            ulonglong2 wv0 = ((const ulonglong2*)(wbase + (k4 + 0) * DOUT))[jc];
            ulonglong2 wv1 = ((const ulonglong2*)(wbase + (k4 + 1) * DOUT))[jc];
            ulonglong2 wv2 = ((const ulonglong2*)(wbase + (k4 + 2) * DOUT))[jc];
            ulonglong2 wv3 = ((const ulonglong2*)(wbase + (k4 + 3) * DOUT))[jc];
            #pragma unroll
            for (int t = 0; t < NT; t++) {
                float4 xv = *(const float4*)(&sx[w][t][h][k4]);
                unsigned long long x0 = pk2(xv.x), x1 = pk2(xv.y);
                unsigned long long x2 = pk2(xv.z), x3 = pk2(xv.w);
                ffma2(p01[t], x0, wv0.x); ffma2(p23[t], x0, wv0.y);
                ffma2(p01[t], x1, wv1.x); ffma2(p23[t], x1, wv1.y);
                ffma2(p01[t], x2, wv2.x); ffma2(p23[t], x2, wv2.y);
                ffma2(p01[t], x3, wv3.x); ffma2(p23[t], x3, wv3.y);
            }
        }

        float4 bv = ((const float4*)(sB + h * DOUT))[jc];
        #pragma unroll
        for (int t = 0; t < NT; t++) {
            int n = nb + t;
            float2 a01 = upk2(p01[t]), a23 = upk2(p23[t]);
            float4 v;
            v.x = a01.x + bv.x; v.x = v.x > 0.f ? v.x : 0.01f * v.x;
            v.y = a01.y + bv.y; v.y = v.y > 0.f ? v.y : 0.01f * v.y;
            v.z = a23.x + bv.z; v.z = v.z > 0.f ? v.z : 0.01f * v.z;
            v.w = a23.y + bv.w; v.w = v.w > 0.f ? v.w : 0.01f * v.w;
            float4 o;
            o.x = v.x + __shfl_xor_sync(0xffffffffu, v.x, 16);
            o.y = v.y + __shfl_xor_sync(0xffffffffu, v.y, 16);
            o.z = v.z + __shfl_xor_sync(0xffffffffu, v.z, 16);
            o.w = v.w + __shfl_xor_sync(0xffffffffu, v.w, 16);
            float ss = o.x * o.x + o.y * o.y + o.z * o.z + o.w * o.w;
            #pragma unroll
            for (int off = LPM / 2; off > 0; off >>= 1)
                ss += __shfl_xor_sync(0xffffffffu, ss, off);
            float inv = 1.0f / fmaxf(sqrtf(ss), 1e-12f);
            if (n < NN && h == 0 && jl < LPM) {
                ((float4*)(dst + (size_t)n * DOUT))[jl] = o;
                float4 on = make_float4(o.x * inv, o.y * inv, o.z * inv, o.w * inv);
                ((float4*)(g_all + (size_t)n * TOT + OFF))[jl] = on;
            }
        }
        __syncwarp();
    }
}

// ---------------------------------------------------------------------------
// Launch 6: scoring + reset g_deg/g_total for the next call (grid covers NN).
__global__ void k_score(const int* __restrict__ users, const int* __restrict__ pos,
                        const int* __restrict__ neg, float* __restrict__ out) {
    int gi = blockIdx.x * blockDim.x + threadIdx.x;
    if (gi < NN) g_deg[gi] = 0;
    if (gi == 0) g_total = 0;

    int wid  = gi >> 5;
    int lane = threadIdx.x & 31;
    if (wid >= NB) return;
    const float* u = g_all + (size_t)users[wid] * TOT;
    const float* p = g_all + (size_t)(N_USERS + pos[wid]) * TOT;
    const float* q = g_all + (size_t)(N_USERS + neg[wid]) * TOT;
    float sp = 0.f, sn = 0.f;
    #pragma unroll
    for (int k = lane; k < TOT; k += 32) {
        float uv = u[k];
        sp += uv * p[k];
        sn += uv * q[k];
    }
    #pragma unroll
    for (int o = 16; o > 0; o >>= 1) {
        sp += __shfl_xor_sync(0xffffffffu, sp, o);
        sn += __shfl_xor_sync(0xffffffffu, sn, o);
    }
    if (lane == 0) { out[2 * wid] = sp; out[2 * wid + 1] = sn; }
}

// ---------------------------------------------------------------------------
extern "C" void kernel_launch(void* const* d_in, const int* in_sizes, int n_in,
                              void* d_out, int out_size) {
    const int*   users = (const int*)  d_in[0];
    const int*   pos   = (const int*)  d_in[1];
    const int*   neg   = (const int*)  d_in[2];
    const int*   rows  = (const int*)  d_in[3];
    const int*   cols  = (const int*)  d_in[4];
    const float* vals  = (const float*)d_in[5];
    const float* ue    = (const float*)d_in[6];
    const float* ee    = (const float*)d_in[7];
    const float* W[3][4];
    for (int l = 0; l < 3; l++)
        for (int j = 0; j < 4; j++)
            W[l][j] = (const float*)d_in[8 + 4 * l + j];

    float *p_ego, *p_ego2;
    cudaGetSymbolAddress((void**)&p_ego,  g_ego);
    cudaGetSymbolAddress((void**)&p_ego2, g_ego2);

    const int TB  = 256;
    const int TBL = 256;   // 8 warps per block for k_layer
    const int GL  = 592;   // 4 blocks/SM * 148 SMs

    // dynamic smem: weights (2*DIN*DOUT) + node tiles (WPB*NT*2*DIN), floats.
    // Rule: <= ~55KB/block keeps 4 blocks/SM (227KB carveout, ~1KB/block reserve).
    const int SM0 = (2 * 64 * 64 + 8 * 4 * 2 * 64) * 4;   // 49152, NT=4
    const int SM1 = (2 * 64 * 32 + 8 * 6 * 2 * 64) * 4;   // 40960, NT=6
    const int SM2 = (2 * 32 * 16 + 8 * 8 * 2 * 32) * 4;   // 20480, NT=8
    cudaFuncSetAttribute(k_layer<64, 64,  64, 4>, cudaFuncAttributeMaxDynamicSharedMemorySize, SM0);
    cudaFuncSetAttribute(k_layer<64, 32, 128, 6>, cudaFuncAttributeMaxDynamicSharedMemorySize, SM1);
    cudaFuncSetAttribute(k_layer<32, 16, 160, 8>, cudaFuncAttributeMaxDynamicSharedMemorySize, SM2);

    // 0: init + histogram
    k_init_hist<<<(NN * 16 + TB - 1) / TB, TB>>>(ue, ee, rows);
    // 1: rowptr by atomic allocation
    k_alloc<<<(NN + TB - 1) / TB, TB>>>();
    // 2: CSR placement
    k_place<<<(NE + TB - 1) / TB, TB>>>(rows, cols, vals);

    // 3-5: fused layers  (launch index 3 = ncu capture slot)
    k_layer<64, 64,  64, 4><<<GL, TBL, SM0>>>(W[0][0], W[0][1], W[0][2], W[0][3], p_ego,  p_ego2);
    k_layer<64, 32, 128, 6><<<GL, TBL, SM1>>>(W[1][0], W[1][1], W[1][2], W[1][3], p_ego2, p_ego);
    k_layer<32, 16, 160, 8><<<GL, TBL, SM2>>>(W[2][0], W[2][1], W[2][2], W[2][3], p_ego,  p_ego2);

    // 6: score + scratch reset
    k_score<<<(NB * 32 + TB - 1) / TB, TB>>>(users, pos, neg, (float*)d_out);
}

// round 17
// speedup vs baseline: 1.6356x; 1.0025x over previous
#include <cuda_runtime.h>

#define N_USERS 50000
#define N_ENT   150000
#define NN      200000
#define NE      2000000
#define NB      8192
#define TOT     176   // 64 + 64 + 32 + 16

// Scratch (allocation-free rule: __device__ globals; zero-initialized at load)
__device__ float g_ego [NN * 64];
__device__ float g_ego2[NN * 64];
__device__ float g_all [NN * TOT];
__device__ int   g_deg   [NN];
__device__ int   g_off   [NN];     // working copy of rowptr for placement
__device__ int   g_rowptr[NN];
__device__ int   g_total;
__device__ int2  g_edge  [NE];     // (col, bitcast(val)) grouped by row

// ---------------------------------------------------------------------------
// packed f32x2 helpers (FFMA2 only reachable via PTX)
__device__ __forceinline__ unsigned long long pk2(float a) {
    unsigned long long r;
    asm("mov.b64 %0, {%1, %1};" : "=l"(r) : "f"(a));
    return r;
}
__device__ __forceinline__ void ffma2(unsigned long long& d,
                                      unsigned long long a, unsigned long long b) {
    asm("fma.rn.f32x2 %0, %1, %2, %0;" : "+l"(d) : "l"(a), "l"(b));
}
__device__ __forceinline__ float2 upk2(unsigned long long v) {
    float x, y;
    asm("mov.b64 {%0, %1}, %2;" : "=f"(x), "=f"(y) : "l"(v));
    return make_float2(x, y);
}

// vector load/store helpers (V = floats per lane: 4 or 2)
template<int V> __device__ __forceinline__ void vload(float* d, const float* p);
template<> __device__ __forceinline__ void vload<4>(float* d, const float* p) {
    float4 t = *(const float4*)p; d[0] = t.x; d[1] = t.y; d[2] = t.z; d[3] = t.w;
}
template<> __device__ __forceinline__ void vload<2>(float* d, const float* p) {
    float2 t = *(const float2*)p; d[0] = t.x; d[1] = t.y;
}
template<int V> __device__ __forceinline__ void vstore(float* p, const float* s);
template<> __device__ __forceinline__ void vstore<4>(float* p, const float* s) {
    *(float4*)p = make_float4(s[0], s[1], s[2], s[3]);
}
template<> __device__ __forceinline__ void vstore<2>(float* p, const float* s) {
    *(float2*)p = make_float2(s[0], s[1]);
}

// ---------------------------------------------------------------------------
// Launch 0: ego/all init + degree histogram (g_deg zeroed by previous call's
// k_score; zero-initialized for the very first call).
// g_all slice is write-once data (read only by k_score at the end) -> stream
// it past L2 so it doesn't evict gather-hot rows.
__global__ void k_init_hist(const float* __restrict__ ue, const float* __restrict__ ee,
                            const int* __restrict__ rows) {
    int i = blockIdx.x * blockDim.x + threadIdx.x;   // over NN*16 = 3.2M
    if (i < NN * 16) {
        int n = i >> 4, c = i & 15;
        float4 v = (n < N_USERS)
            ? ((const float4*)ue)[(size_t)n * 16 + c]
            : ((const float4*)ee)[(size_t)(n - N_USERS) * 16 + c];
        ((float4*)g_ego)[i] = v;                               // src of layer0: cached
        __stcs(((float4*)(g_all + (size_t)n * TOT)) + c, v);   // streamed
    }
    if (i < NE) atomicAdd(&g_deg[rows[i]], 1);
}

// Launch 1: rowptr by atomic allocation (order-free; rows only need contiguity)
__global__ void k_alloc() {
    int n = blockIdx.x * blockDim.x + threadIdx.x;
    if (n >= NN) return;
    int d  = g_deg[n];
    int rp = atomicAdd(&g_total, d);
    g_rowptr[n] = rp;
    g_off[n]    = rp;
}

// Launch 2: scatter edges into CSR slots
__global__ void k_place(const int* __restrict__ rows, const int* __restrict__ cols,
                        const float* __restrict__ vals) {
    int e = blockIdx.x * blockDim.x + threadIdx.x;
    if (e >= NE) return;
    int r = rows[e];
    int p = atomicAdd(&g_off[r], 1);
    g_edge[p] = make_int2(cols[e], __float_as_int(vals[e]));
}

// ---------------------------------------------------------------------------
// Launches 3-5: fused side-gather + GC/BI transform + l2norm.
// Gather (round-13 proven): HALF-WARP per node, LOCKSTEP to warp-max degree
// with (0,0)-padded edges (one warp-wide LDG serves both halves); 2-way unroll.
// Matmul: node-tiled (per-layer NT) + packed FFMA2; lanes 0-15 GC, 16-31 BI.
// g_all output streamed (evict-first) to preserve L2 for src/dst rows.
template<int DIN, int DOUT, int OFF, int NT>
__global__ void __launch_bounds__(256, 4)
k_layer(const float* __restrict__ Wg, const float* __restrict__ bg,
        const float* __restrict__ Wb, const float* __restrict__ bb,
        const float* __restrict__ src, float* __restrict__ dst) {
    constexpr int V4  = DIN / 16;       // floats per lane in half-warp (4 or 2)
    constexpr int LPM = DOUT / 4;       // active lanes per matrix
    constexpr int WPB = 8;
    extern __shared__ __align__(16) float sdyn[];
    float* sW = sdyn;                                   // 2*DIN*DOUT
    typedef float SxTile[NT][2][DIN];
    SxTile* sx = reinterpret_cast<SxTile*>(sdyn + 2 * DIN * DOUT);  // [WPB]
    __shared__ __align__(16) float sB[2 * DOUT];

    int tid = threadIdx.x;
    for (int i = tid; i < DIN * DOUT; i += blockDim.x) { sW[i] = Wg[i]; sW[DIN * DOUT + i] = Wb[i]; }
    for (int i = tid; i < DOUT; i += blockDim.x)       { sB[i] = bg[i]; sB[DOUT + i] = bb[i]; }
    __syncthreads();

    int w = tid >> 5, lane = tid & 31;
    int h  = lane >> 4;                 // half id: gather node select / matmul GC-BI
    int jl = lane & 15;
    int jc = (jl < LPM) ? jl : 0;
    const float* wbase = sW + h * DIN * DOUT;

    for (int nb = (blockIdx.x * WPB + w) * NT; nb < NN; nb += gridDim.x * WPB * NT) {
        // ---- gather NT nodes, two at a time (one per half-warp), lockstep ----
        #pragma unroll 1
        for (int tp = 0; tp < NT; tp += 2) {
            int n = nb + tp + h;
            bool act = n < NN;
            float er[V4], a0[V4], a1[V4];
            #pragma unroll
            for (int c = 0; c < V4; c++) { er[c] = 0.f; a0[c] = 0.f; a1[c] = 0.f; }
            int s0 = 0, cnt = 0;
            if (act) {
                s0  = g_rowptr[n];
                cnt = g_deg[n];
                vload<V4>(er, src + (size_t)n * DIN + V4 * jl);
            }
            int cmax = cnt;
            #pragma unroll
            for (int o = 16; o > 0; o >>= 1)
                cmax = max(cmax, __shfl_xor_sync(0xffffffffu, cmax, o));
            for (int m = 0; m < cmax; m += 2) {
                int2 e0 = (m     < cnt) ? __ldg(&g_edge[s0 + m])     : make_int2(0, 0);
                int2 e1 = (m + 1 < cnt) ? __ldg(&g_edge[s0 + m + 1]) : make_int2(0, 0);
                float x0[V4], x1[V4];
                vload<V4>(x0, src + (size_t)e0.x * DIN + V4 * jl);
                vload<V4>(x1, src + (size_t)e1.x * DIN + V4 * jl);
                float v0 = __int_as_float(e0.y);
                float v1 = __int_as_float(e1.y);
                #pragma unroll
                for (int c = 0; c < V4; c++) {
                    a0[c] = fmaf(v0, x0[c], a0[c]);
                    a1[c] = fmaf(v1, x1[c], a1[c]);
                }
            }
            float s1v[V4], s2v[V4];
            #pragma unroll
            for (int c = 0; c < V4; c++) {
                float acc = a0[c] + a1[c];
                s1v[c] = er[c] + acc;
                s2v[c] = er[c] * acc;
            }
            vstore<V4>(&sx[w][tp + h][0][V4 * jl], s1v);
            vstore<V4>(&sx[w][tp + h][1][V4 * jl], s2v);
        }
        __syncwarp();

        // ---- node-tiled matmul with packed FFMA2 (wv-preload form) ----
        unsigned long long p01[NT], p23[NT];
        #pragma unroll
        for (int t = 0; t < NT; t++) { p01[t] = 0ull; p23[t] = 0ull; }

        #pragma unroll 2
        for (int k4 = 0; k4 < DIN; k4 += 4) {
            ulonglong2 wv0 = ((const ulonglong2*)(wbase + (k4 + 0) * DOUT))[jc];
            ulonglong2 wv1 = ((const ulonglong2*)(wbase + (k4 + 1) * DOUT))[jc];
            ulonglong2 wv2 = ((const ulonglong2*)(wbase + (k4 + 2) * DOUT))[jc];
            ulonglong2 wv3 = ((const ulonglong2*)(wbase + (k4 + 3) * DOUT))[jc];
            #pragma unroll
            for (int t = 0; t < NT; t++) {
                float4 xv = *(const float4*)(&sx[w][t][h][k4]);
                unsigned long long x0 = pk2(xv.x), x1 = pk2(xv.y);
                unsigned long long x2 = pk2(xv.z), x3 = pk2(xv.w);
                ffma2(p01[t], x0, wv0.x); ffma2(p23[t], x0, wv0.y);
                ffma2(p01[t], x1, wv1.x); ffma2(p23[t], x1, wv1.y);
                ffma2(p01[t], x2, wv2.x); ffma2(p23[t], x2, wv2.y);
                ffma2(p01[t], x3, wv3.x); ffma2(p23[t], x3, wv3.y);
            }
        }

        float4 bv = ((const float4*)(sB + h * DOUT))[jc];
        #pragma unroll
        for (int t = 0; t < NT; t++) {
            int n = nb + t;
            float2 a01 = upk2(p01[t]), a23 = upk2(p23[t]);
            float4 v;
            v.x = a01.x + bv.x; v.x = v.x > 0.f ? v.x : 0.01f * v.x;
            v.y = a01.y + bv.y; v.y = v.y > 0.f ? v.y : 0.01f * v.y;
            v.z = a23.x + bv.z; v.z = v.z > 0.f ? v.z : 0.01f * v.z;
            v.w = a23.y + bv.w; v.w = v.w > 0.f ? v.w : 0.01f * v.w;
            float4 o;
            o.x = v.x + __shfl_xor_sync(0xffffffffu, v.x, 16);
            o.y = v.y + __shfl_xor_sync(0xffffffffu, v.y, 16);
            o.z = v.z + __shfl_xor_sync(0xffffffffu, v.z, 16);
            o.w = v.w + __shfl_xor_sync(0xffffffffu, v.w, 16);
            float ss = o.x * o.x + o.y * o.y + o.z * o.z + o.w * o.w;
            #pragma unroll
            for (int off = LPM / 2; off > 0; off >>= 1)
                ss += __shfl_xor_sync(0xffffffffu, ss, off);
            float inv = 1.0f / fmaxf(sqrtf(ss), 1e-12f);
            if (n < NN && h == 0 && jl < LPM) {
                ((float4*)(dst + (size_t)n * DOUT))[jl] = o;   // next layer's src: cached
                float4 on = make_float4(o.x * inv, o.y * inv, o.z * inv, o.w * inv);
                __stcs(((float4*)(g_all + (size_t)n * TOT + OFF)) + jl, on);  // streamed
            }
        }
        __syncwarp();
    }
}

// ---------------------------------------------------------------------------
// Launch 6: scoring + reset g_deg/g_total for the next call (grid covers NN).
__global__ void k_score(const int* __restrict__ users, const int* __restrict__ pos,
                        const int* __restrict__ neg, float* __restrict__ out) {
    int gi = blockIdx.x * blockDim.x + threadIdx.x;
    if (gi < NN) g_deg[gi] = 0;
    if (gi == 0) g_total = 0;

    int wid  = gi >> 5;
    int lane = threadIdx.x & 31;
    if (wid >= NB) return;
    const float* u = g_all + (size_t)users[wid] * TOT;
    const float* p = g_all + (size_t)(N_USERS + pos[wid]) * TOT;
    const float* q = g_all + (size_t)(N_USERS + neg[wid]) * TOT;
    float sp = 0.f, sn = 0.f;
    #pragma unroll
    for (int k = lane; k < TOT; k += 32) {
        float uv = u[k];
        sp += uv * p[k];
        sn += uv * q[k];
    }
    #pragma unroll
    for (int o = 16; o > 0; o >>= 1) {
        sp += __shfl_xor_sync(0xffffffffu, sp, o);
        sn += __shfl_xor_sync(0xffffffffu, sn, o);
    }
    if (lane == 0) { out[2 * wid] = sp; out[2 * wid + 1] = sn; }
}

// ---------------------------------------------------------------------------
extern "C" void kernel_launch(void* const* d_in, const int* in_sizes, int n_in,
                              void* d_out, int out_size) {
    const int*   users = (const int*)  d_in[0];
    const int*   pos   = (const int*)  d_in[1];
    const int*   neg   = (const int*)  d_in[2];
    const int*   rows  = (const int*)  d_in[3];
    const int*   cols  = (const int*)  d_in[4];
    const float* vals  = (const float*)d_in[5];
    const float* ue    = (const float*)d_in[6];
    const float* ee    = (const float*)d_in[7];
    const float* W[3][4];
    for (int l = 0; l < 3; l++)
        for (int j = 0; j < 4; j++)
            W[l][j] = (const float*)d_in[8 + 4 * l + j];

    float *p_ego, *p_ego2;
    cudaGetSymbolAddress((void**)&p_ego,  g_ego);
    cudaGetSymbolAddress((void**)&p_ego2, g_ego2);

    const int TB  = 256;
    const int TBL = 256;   // 8 warps per block for k_layer
    const int GL  = 592;   // 4 blocks/SM * 148 SMs

    // dynamic smem: weights (2*DIN*DOUT) + node tiles (WPB*NT*2*DIN), floats.
    // Rule: <= ~55KB/block keeps 4 blocks/SM (227KB carveout, ~1KB/block reserve).
    const int SM0 = (2 * 64 * 64 + 8 * 4 * 2 * 64) * 4;   // 49152, NT=4
    const int SM1 = (2 * 64 * 32 + 8 * 6 * 2 * 64) * 4;   // 40960, NT=6
    const int SM2 = (2 * 32 * 16 + 8 * 8 * 2 * 32) * 4;   // 20480, NT=8
    cudaFuncSetAttribute(k_layer<64, 64,  64, 4>, cudaFuncAttributeMaxDynamicSharedMemorySize, SM0);
    cudaFuncSetAttribute(k_layer<64, 32, 128, 6>, cudaFuncAttributeMaxDynamicSharedMemorySize, SM1);
    cudaFuncSetAttribute(k_layer<32, 16, 160, 8>, cudaFuncAttributeMaxDynamicSharedMemorySize, SM2);

    // 0: init + histogram
    k_init_hist<<<(NN * 16 + TB - 1) / TB, TB>>>(ue, ee, rows);
    // 1: rowptr by atomic allocation
    k_alloc<<<(NN + TB - 1) / TB, TB>>>();
    // 2: CSR placement
    k_place<<<(NE + TB - 1) / TB, TB>>>(rows, cols, vals);

    // 3-5: fused layers  (launch index 3 = ncu capture slot)
    k_layer<64, 64,  64, 4><<<GL, TBL, SM0>>>(W[0][0], W[0][1], W[0][2], W[0][3], p_ego,  p_ego2);
    k_layer<64, 32, 128, 6><<<GL, TBL, SM1>>>(W[1][0], W[1][1], W[1][2], W[1][3], p_ego2, p_ego);
    k_layer<32, 16, 160, 8><<<GL, TBL, SM2>>>(W[2][0], W[2][1], W[2][2], W[2][3], p_ego,  p_ego2);

    // 6: score + scratch reset
    k_score<<<(NB * 32 + TB - 1) / TB, TB>>>(users, pos, neg, (float*)d_out);
}